// round 10
// baseline (speedup 1.0000x reference)
#include <cuda_runtime.h>
#include <cuda_bf16.h>
#include <math_constants.h>
#include <cstdint>
#include <cstddef>

#define BATCH 16
#define TQ 800
#define TK 200

// ---------------------------------------------------------------------------
// Device-global scratch (no allocations allowed)
// ---------------------------------------------------------------------------
__device__ __align__(16) __nv_bfloat16 g_kcol [BATCH * TK * 1536];   // im2col(keys)
__device__ __align__(16) __nv_bfloat16 g_qbf  [BATCH * 80  * TQ];
__device__ __align__(16) __nv_bfloat16 g_kW1bf[1024 * 1536];
__device__ __align__(16) __nv_bfloat16 g_kW2bf[80 * 1024];
__device__ __align__(16) __nv_bfloat16 g_qW1bf[160 * 240];
__device__ __align__(16) __nv_bfloat16 g_qW2bf[80 * 160];
__device__ __align__(16) __nv_bfloat16 g_qW3bf[80 * 80];
__device__ float g_kenc[BATCH * 80 * TK];
__device__ float g_qenc[BATCH * 80 * TQ];

__device__ __forceinline__ uint32_t smem_to_u32(const void* p) {
    uint32_t a;
    asm("{ .reg .u64 t; cvta.to.shared.u64 t, %1; cvt.u32.u64 %0, t; }" : "=r"(a) : "l"(p));
    return a;
}
__device__ __forceinline__ void ldsm_x4(uint32_t& r0, uint32_t& r1, uint32_t& r2, uint32_t& r3,
                                        uint32_t addr) {
    asm volatile("ldmatrix.sync.aligned.m8n8.x4.shared.b16 {%0,%1,%2,%3}, [%4];"
                 : "=r"(r0), "=r"(r1), "=r"(r2), "=r"(r3) : "r"(addr));
}
__device__ __forceinline__ void mma_bf16(float* c, uint32_t a0, uint32_t a1, uint32_t a2, uint32_t a3,
                                         uint32_t b0, uint32_t b1) {
    asm volatile("mma.sync.aligned.m16n8k16.row.col.f32.bf16.bf16.f32 "
                 "{%0,%1,%2,%3}, {%4,%5,%6,%7}, {%8,%9}, {%0,%1,%2,%3};"
                 : "+f"(c[0]), "+f"(c[1]), "+f"(c[2]), "+f"(c[3])
                 : "r"(a0), "r"(a1), "r"(a2), "r"(a3), "r"(b0), "r"(b1));
}
__device__ __forceinline__ void cp16(uint32_t dst, const void* src) {
    asm volatile("cp.async.ca.shared.global [%0], [%1], 16;" :: "r"(dst), "l"(src));
}
__device__ __forceinline__ void cp_commit() {
    asm volatile("cp.async.commit_group;" ::: "memory");
}

// ===========================================================================
// im2col(keys) via smem staging: CTA per (b, 25-t tile).
// Phase 1: keys[b][:, t0-1..t0+25] -> smem (mostly-coalesced f32 reads).
// Phase 2: fully-coalesced 16B kcol writes, gather resolved in smem.
// ===========================================================================
#define IC_TILE 25
#define IC_SMEM (512 * 28 * 4)   // 57344 B

__global__ __launch_bounds__(256)
void im2col_keys(const float* __restrict__ keys)
{
    extern __shared__ float ks[];       // [512][28]
    const int b    = blockIdx.x >> 3;
    const int tile = blockIdx.x & 7;
    const int t0   = tile * IC_TILE;
    const int tid  = threadIdx.x;

    for (int idx = tid; idx < 512 * 27; idx += 256) {
        const int ci = idx / 27;
        const int j  = idx - ci * 27;
        const int tg = t0 - 1 + j;
        ks[ci * 28 + j] = (tg >= 0 && tg < TK) ? keys[((size_t)b * 512 + ci) * TK + tg] : 0.f;
    }
    __syncthreads();

    for (int e = tid; e < IC_TILE * 192; e += 256) {
        const int tt = e / 192;
        const int c  = e - tt * 192;
        const int kc = c * 8;
        __nv_bfloat16 v[8];
        #pragma unroll
        for (int i = 0; i < 8; i++) {
            const int k  = kc + i;
            const int ci = k / 3;
            const int w  = k - ci * 3;
            v[i] = __float2bfloat16(ks[ci * 28 + tt + w]);
        }
        const int n = b * TK + t0 + tt;
        *reinterpret_cast<uint4*>(&g_kcol[(size_t)n * 1536 + kc]) = *reinterpret_cast<uint4*>(v);
    }
}

// ===========================================================================
// Keys-path weight conversion (runs on stream B, overlapping im2col)
// ===========================================================================
#define CK_S2 (1024 * 1536)
#define CK_S3 (80 * 1024)
#define CK_TOT (CK_S2 + CK_S3)

__global__ __launch_bounds__(256)
void convert_k(const float* __restrict__ kW1, const float* __restrict__ kW2)
{
    const long e = ((long)blockIdx.x * 256 + threadIdx.x) * 4;
    if (e >= CK_TOT) return;
    const float* src; __nv_bfloat16* dst; long off;
    if (e < CK_S2) { src = kW1; dst = g_kW1bf; off = e; }
    else           { src = kW2; dst = g_kW2bf; off = e - CK_S2; }
    const float4 v = *reinterpret_cast<const float4*>(src + off);
    __nv_bfloat162* d2 = reinterpret_cast<__nv_bfloat162*>(dst + off);
    d2[0] = __float22bfloat162_rn(make_float2(v.x, v.y));
    d2[1] = __float22bfloat162_rn(make_float2(v.z, v.w));
}

// ===========================================================================
// Query-path conversion
// ===========================================================================
#define CQ_S1 (BATCH * 80 * TQ)
#define CQ_S4 (160 * 240)
#define CQ_S5 (80 * 160)
#define CQ_S6 (80 * 80)
#define CQ_O4 (CQ_S1)
#define CQ_O5 (CQ_O4 + CQ_S4)
#define CQ_O6 (CQ_O5 + CQ_S5)
#define CQ_TOT (CQ_O6 + CQ_S6)

__global__ __launch_bounds__(256)
void convert_q(const float* __restrict__ queries, const float* __restrict__ qW1,
               const float* __restrict__ qW2, const float* __restrict__ qW3)
{
    const long e = ((long)blockIdx.x * 256 + threadIdx.x) * 4;
    if (e >= CQ_TOT) return;
    const float* src; __nv_bfloat16* dst; long off;
    if      (e < CQ_O4) { src = queries; dst = g_qbf;   off = e; }
    else if (e < CQ_O5) { src = qW1;     dst = g_qW1bf; off = e - CQ_O4; }
    else if (e < CQ_O6) { src = qW2;     dst = g_qW2bf; off = e - CQ_O5; }
    else                { src = qW3;     dst = g_qW3bf; off = e - CQ_O6; }
    const float4 v = *reinterpret_cast<const float4*>(src + off);
    __nv_bfloat162* d2 = reinterpret_cast<__nv_bfloat162*>(dst + off);
    d2[0] = __float22bfloat162_rn(make_float2(v.x, v.y));
    d2[1] = __float22bfloat162_rn(make_float2(v.z, v.w));
}

__global__ __launch_bounds__(256)
void init_kenc(const float* __restrict__ kb2)
{
    const int idx = blockIdx.x * 256 + threadIdx.x;
    if (idx < BATCH * 80 * TK)
        g_kenc[idx] = kb2[(idx / TK) % 80];
}

// ===========================================================================
// keys conv1 (512->1024,k3) + fused pointwise conv2 (unchanged from R7/R8)
// ===========================================================================
#define C1_K   1536
#define C1_LD  72
#define C2_LD  136
#define C1_SMEM 82944

__global__ __launch_bounds__(256)
void conv1_fused(const __nv_bfloat16* __restrict__ kcol, const __nv_bfloat16* __restrict__ W1,
                 const float* __restrict__ bias1, const __nv_bfloat16* __restrict__ W2,
                 float* __restrict__ kenc)
{
    extern __shared__ char dsm[];
    const uint32_t smb = smem_to_u32(dsm);
    const int tid  = threadIdx.x;
    const int wid  = tid >> 5;
    const int lane = tid & 31;
    const int m0 = blockIdx.y * 128;
    const int n0 = blockIdx.x * 64;
    const int warp_m = wid >> 1;
    const int warp_n = wid & 1;

    auto prefetch = [&](int ch, int st) {
        const int k0 = ch * 64;
        const uint32_t Ab = smb + st * 18432;
        const uint32_t Bb = smb + 55296 + st * 9216;
        #pragma unroll
        for (int j = 0; j < 4; j++) {
            const int e  = tid + 256 * j;
            const int r  = e >> 3;
            const int kq = (e & 7) << 3;
            cp16(Ab + (r * C1_LD + kq) * 2, W1 + (size_t)(m0 + r) * C1_K + k0 + kq);
        }
        #pragma unroll
        for (int j = 0; j < 2; j++) {
            const int e  = tid + 256 * j;
            const int r  = e >> 3;
            const int kq = (e & 7) << 3;
            cp16(Bb + (r * C1_LD + kq) * 2, kcol + (size_t)(n0 + r) * C1_K + k0 + kq);
        }
        cp_commit();
    };

    float acc[2][4][4];
    #pragma unroll
    for (int mt = 0; mt < 2; mt++)
        #pragma unroll
        for (int nt = 0; nt < 4; nt++)
            #pragma unroll
            for (int i = 0; i < 4; i++) acc[mt][nt][i] = 0.f;

    prefetch(0, 0);
    prefetch(1, 1);

    const uint32_t a_lane = ((warp_m * 32 + (lane & 15)) * C1_LD + (lane >> 4) * 8) * 2;
    const uint32_t b_lane = ((warp_n * 32 + (lane & 15)) * C1_LD + (lane >> 4) * 8) * 2;

    for (int ch = 0; ch < 24; ch++) {
        if (ch < 23) asm volatile("cp.async.wait_group 1;" ::: "memory");
        else         asm volatile("cp.async.wait_group 0;" ::: "memory");
        __syncthreads();

        const int st = ch % 3;
        const uint32_t a_addr0 = smb + st * 18432 + a_lane;
        const uint32_t b_addr0 = smb + 55296 + st * 9216 + b_lane;

        #pragma unroll
        for (int ks = 0; ks < 4; ks++) {
            const uint32_t koff = ks * 32;
            uint32_t a[2][4], b[2][4];
            #pragma unroll
            for (int mt = 0; mt < 2; mt++)
                ldsm_x4(a[mt][0], a[mt][1], a[mt][2], a[mt][3],
                        a_addr0 + mt * 16 * C1_LD * 2 + koff);
            #pragma unroll
            for (int np = 0; np < 2; np++)
                ldsm_x4(b[np][0], b[np][1], b[np][2], b[np][3],
                        b_addr0 + np * 16 * C1_LD * 2 + koff);
            #pragma unroll
            for (int mt = 0; mt < 2; mt++)
                #pragma unroll
                for (int np = 0; np < 2; np++) {
                    mma_bf16(acc[mt][np * 2 + 0], a[mt][0], a[mt][1], a[mt][2], a[mt][3],
                             b[np][0], b[np][2]);
                    mma_bf16(acc[mt][np * 2 + 1], a[mt][0], a[mt][1], a[mt][2], a[mt][3],
                             b[np][1], b[np][3]);
                }
        }
        if (ch + 2 < 24) prefetch(ch + 2, (ch + 2) % 3);
    }
    __syncthreads();

    __nv_bfloat16* Sh  = reinterpret_cast<__nv_bfloat16*>(dsm);
    __nv_bfloat16* W2s = reinterpret_cast<__nv_bfloat16*>(dsm + 17408);

    #pragma unroll
    for (int mt = 0; mt < 2; mt++) {
        const int col = warp_m * 32 + mt * 16 + (lane >> 2);
        const float bv0 = bias1[m0 + col];
        const float bv1 = bias1[m0 + col + 8];
        #pragma unroll
        for (int nt = 0; nt < 4; nt++) {
            const int nb = warp_n * 32 + (nt >> 1) * 16 + (nt & 1) * 8 + ((lane & 3) << 1);
            #pragma unroll
            for (int cc = 0; cc < 2; cc++) {
                Sh[(nb + cc) * C2_LD + col]     = __float2bfloat16(fmaxf(acc[mt][nt][cc]     + bv0, 0.f));
                Sh[(nb + cc) * C2_LD + col + 8] = __float2bfloat16(fmaxf(acc[mt][nt][2 + cc] + bv1, 0.f));
            }
        }
    }
    for (int e = tid; e < 80 * 32; e += 256) {
        const int r = e >> 5;
        const int q = (e & 31) << 2;
        *reinterpret_cast<uint2*>(&W2s[r * C2_LD + q]) =
            *reinterpret_cast<const uint2*>(W2 + (size_t)r * 1024 + m0 + q);
    }
    __syncthreads();

    if (wid < 4) {
        const uint32_t sh_addr = smem_to_u32(Sh)  + ((wid * 16 + (lane & 15)) * C2_LD + (lane >> 4) * 8) * 2;
        const uint32_t w2_addr = smem_to_u32(W2s) + ((lane & 15) * C2_LD + (lane >> 4) * 8) * 2;
        float acc2[5][2][4];
        #pragma unroll
        for (int ct = 0; ct < 5; ct++)
            #pragma unroll
            for (int s = 0; s < 2; s++)
                #pragma unroll
                for (int i = 0; i < 4; i++) acc2[ct][s][i] = 0.f;

        #pragma unroll
        for (int ks = 0; ks < 8; ks++) {
            const uint32_t koff = ks * 32;
            uint32_t a0, a1, a2, a3;
            ldsm_x4(a0, a1, a2, a3, sh_addr + koff);
            #pragma unroll
            for (int ct = 0; ct < 5; ct++) {
                uint32_t b0, b1, b2, b3;
                ldsm_x4(b0, b1, b2, b3, w2_addr + ct * 16 * C2_LD * 2 + koff);
                mma_bf16(acc2[ct][0], a0, a1, a2, a3, b0, b2);
                mma_bf16(acc2[ct][1], a0, a1, a2, a3, b1, b3);
            }
        }
        #pragma unroll
        for (int ct = 0; ct < 5; ct++)
            #pragma unroll
            for (int s = 0; s < 2; s++)
                #pragma unroll
                for (int i = 0; i < 4; i++) {
                    const int co2 = ct * 16 + s * 8 + ((lane & 3) << 1) + (i & 1);
                    const int n   = n0 + wid * 16 + (lane >> 2) + ((i >> 1) << 3);
                    const int bb  = n / TK;
                    const int t   = n - bb * TK;
                    atomicAdd(kenc + ((size_t)bb * 80 + co2) * TK + t, acc2[ct][s][i]);
                }
    }
}

// ===========================================================================
// FUSED query path, 512 threads (R8 version — best measured).
// ===========================================================================
#define QF_SMEM 185856

__global__ __launch_bounds__(512)
void fused_q(const __nv_bfloat16* __restrict__ qbf,
             const __nv_bfloat16* __restrict__ W1, const float* __restrict__ b1,
             const __nv_bfloat16* __restrict__ W2, const float* __restrict__ b2,
             const __nv_bfloat16* __restrict__ W3, const float* __restrict__ b3,
             float* __restrict__ qenc)
{
    extern __shared__ char dsm[];
    __nv_bfloat16* A1  = reinterpret_cast<__nv_bfloat16*>(dsm);
    __nv_bfloat16* W1s = reinterpret_cast<__nv_bfloat16*>(dsm + 63488);
    __nv_bfloat16* H1  = reinterpret_cast<__nv_bfloat16*>(dsm + 142848);
    __nv_bfloat16* W2s = reinterpret_cast<__nv_bfloat16*>(dsm);
    __nv_bfloat16* H2  = reinterpret_cast<__nv_bfloat16*>(dsm + 26880);
    __nv_bfloat16* W3s = reinterpret_cast<__nv_bfloat16*>(dsm + 49408);

    const int tid  = threadIdx.x;
    const int wid  = tid >> 5;
    const int lane = tid & 31;
    const int n0   = blockIdx.x * 128;
    const int rowq = (lane & 15);
    const int kq8  = (lane >> 4) * 8;

    #pragma unroll
    for (int j = 0; j < 15; j++) {
        const int kl = (tid >> 5) + j * 16;
        const int ci = kl / 3;
        const int w  = kl - ci * 3;
        #pragma unroll
        for (int i = 0; i < 4; i++) {
            const int r  = ((tid & 31) << 2) + i;
            const int n  = n0 + r;
            const int bb = n / TQ;
            const int t  = n - bb * TQ;
            const int tg = t + w - 1;
            __nv_bfloat16 v = __float2bfloat16(0.f);
            if (tg >= 0 && tg < TQ) v = qbf[((size_t)bb * 80 + ci) * TQ + tg];
            A1[r * 248 + kl] = v;
        }
    }
    for (int e = tid; e < 160 * 60; e += 512) {
        const int r = e / 60;
        const int q = (e - r * 60) * 4;
        *reinterpret_cast<uint2*>(&W1s[r * 248 + q]) =
            *reinterpret_cast<const uint2*>(W1 + (size_t)r * 240 + q);
    }
    __syncthreads();

    {
        const int ng  = wid & 7;
        const int coh = (wid >> 3) * 80;
        const uint32_t a_addr = smem_to_u32(A1)  + ((ng * 16 + rowq) * 248 + kq8) * 2;
        const uint32_t b_addr = smem_to_u32(W1s) + ((coh + rowq) * 248 + kq8) * 2;
        float acc1[5][2][4];
        #pragma unroll
        for (int ct = 0; ct < 5; ct++)
            #pragma unroll
            for (int s = 0; s < 2; s++)
                #pragma unroll
                for (int i = 0; i < 4; i++) acc1[ct][s][i] = 0.f;
        #pragma unroll
        for (int ks = 0; ks < 15; ks++) {
            const uint32_t koff = ks * 32;
            uint32_t a0, a1, a2, a3;
            ldsm_x4(a0, a1, a2, a3, a_addr + koff);
            #pragma unroll
            for (int ct = 0; ct < 5; ct++) {
                uint32_t b0, b1, b2, b3;
                ldsm_x4(b0, b1, b2, b3, b_addr + ct * 16 * 248 * 2 + koff);
                mma_bf16(acc1[ct][0], a0, a1, a2, a3, b0, b2);
                mma_bf16(acc1[ct][1], a0, a1, a2, a3, b1, b3);
            }
        }
        __syncthreads();
        #pragma unroll
        for (int ct = 0; ct < 5; ct++)
            #pragma unroll
            for (int s = 0; s < 2; s++)
                #pragma unroll
                for (int i = 0; i < 4; i++) {
                    const int co = coh + ct * 16 + s * 8 + ((lane & 3) << 1) + (i & 1);
                    const int nl = ng * 16 + (lane >> 2) + ((i >> 1) << 3);
                    H1[nl * 168 + co] = __float2bfloat16(fmaxf(acc1[ct][s][i] + b1[co], 0.f));
                }
    }
    for (int e = tid; e < 80 * 40; e += 512) {
        const int r = e / 40;
        const int q = (e - r * 40) * 4;
        *reinterpret_cast<uint2*>(&W2s[r * 168 + q]) =
            *reinterpret_cast<const uint2*>(W2 + (size_t)r * 160 + q);
    }
    __syncthreads();

    if (wid >= 8) {
        for (int e = tid - 256; e < 80 * 20; e += 256) {
            const int r = e / 20;
            const int q = (e - r * 20) * 4;
            *reinterpret_cast<uint2*>(&W3s[r * 88 + q]) =
                *reinterpret_cast<const uint2*>(W3 + (size_t)r * 80 + q);
        }
    } else {
        const uint32_t a_addr = smem_to_u32(H1)  + ((wid * 16 + rowq) * 168 + kq8) * 2;
        const uint32_t b_addr = smem_to_u32(W2s) + (rowq * 168 + kq8) * 2;
        float acc2[5][2][4];
        #pragma unroll
        for (int ct = 0; ct < 5; ct++)
            #pragma unroll
            for (int s = 0; s < 2; s++)
                #pragma unroll
                for (int i = 0; i < 4; i++) acc2[ct][s][i] = 0.f;
        #pragma unroll
        for (int ks = 0; ks < 10; ks++) {
            const uint32_t koff = ks * 32;
            uint32_t a0, a1, a2, a3;
            ldsm_x4(a0, a1, a2, a3, a_addr + koff);
            #pragma unroll
            for (int ct = 0; ct < 5; ct++) {
                uint32_t b0, b1, b2, b3;
                ldsm_x4(b0, b1, b2, b3, b_addr + ct * 16 * 168 * 2 + koff);
                mma_bf16(acc2[ct][0], a0, a1, a2, a3, b0, b2);
                mma_bf16(acc2[ct][1], a0, a1, a2, a3, b1, b3);
            }
        }
        #pragma unroll
        for (int ct = 0; ct < 5; ct++)
            #pragma unroll
            for (int s = 0; s < 2; s++)
                #pragma unroll
                for (int i = 0; i < 4; i++) {
                    const int co = ct * 16 + s * 8 + ((lane & 3) << 1) + (i & 1);
                    const int nl = wid * 16 + (lane >> 2) + ((i >> 1) << 3);
                    H2[nl * 88 + co] = __float2bfloat16(fmaxf(acc2[ct][s][i] + b2[co], 0.f));
                }
    }
    __syncthreads();

    if (wid < 8) {
        const uint32_t a_addr = smem_to_u32(H2)  + ((wid * 16 + rowq) * 88 + kq8) * 2;
        const uint32_t b_addr = smem_to_u32(W3s) + (rowq * 88 + kq8) * 2;
        float acc3[5][2][4];
        #pragma unroll
        for (int ct = 0; ct < 5; ct++)
            #pragma unroll
            for (int s = 0; s < 2; s++)
                #pragma unroll
                for (int i = 0; i < 4; i++) acc3[ct][s][i] = 0.f;
        #pragma unroll
        for (int ks = 0; ks < 5; ks++) {
            const uint32_t koff = ks * 32;
            uint32_t a0, a1, a2, a3;
            ldsm_x4(a0, a1, a2, a3, a_addr + koff);
            #pragma unroll
            for (int ct = 0; ct < 5; ct++) {
                uint32_t b0, b1, b2, b3;
                ldsm_x4(b0, b1, b2, b3, b_addr + ct * 16 * 88 * 2 + koff);
                mma_bf16(acc3[ct][0], a0, a1, a2, a3, b0, b2);
                mma_bf16(acc3[ct][1], a0, a1, a2, a3, b1, b3);
            }
        }
        #pragma unroll
        for (int ct = 0; ct < 5; ct++)
            #pragma unroll
            for (int s = 0; s < 2; s++)
                #pragma unroll
                for (int i = 0; i < 4; i++) {
                    const int co = ct * 16 + s * 8 + ((lane & 3) << 1) + (i & 1);
                    const int n  = n0 + wid * 16 + (lane >> 2) + ((i >> 1) << 3);
                    const int bb = n / TQ;
                    const int t  = n - bb * TQ;
                    qenc[((size_t)bb * 80 + co) * TQ + t] = acc3[ct][s][i] + b3[co];
                }
    }
}

// ---------------------------------------------------------------------------
// Fused attention (R8 version)
// ---------------------------------------------------------------------------
static __device__ __forceinline__ float warp_max(float v) {
    #pragma unroll
    for (int o = 16; o > 0; o >>= 1) v = fmaxf(v, __shfl_xor_sync(0xffffffffu, v, o));
    return v;
}
static __device__ __forceinline__ float warp_sum(float v) {
    #pragma unroll
    for (int o = 16; o > 0; o >>= 1) v += __shfl_xor_sync(0xffffffffu, v, o);
    return v;
}

__global__ __launch_bounds__(256)
void attn_kernel(const float* __restrict__ qenc, const float* __restrict__ kenc,
                 const float* __restrict__ prior, const unsigned char* __restrict__ mask,
                 float* __restrict__ attn_out, float* __restrict__ logp_out)
{
    extern __shared__ float sm[];
    float* Ks  = sm;
    float* Qs  = sm + 80 * TK;
    float* k2s = Qs + 32 * 81;

    const int b   = blockIdx.y;
    const int q0  = blockIdx.x * 32;
    const int tid = threadIdx.x;

    const float* kb = kenc + (size_t)b * 80 * TK;
    for (int i = tid; i < 80 * TK / 4; i += 256)
        reinterpret_cast<float4*>(Ks)[i] = reinterpret_cast<const float4*>(kb)[i];

    const float* qb = qenc + (size_t)b * 80 * TQ;
    {
        const int ql = tid & 31;
        for (int c = tid >> 5; c < 80; c += 8)
            Qs[ql * 81 + c] = qb[c * TQ + q0 + ql];
    }
    __syncthreads();

    for (int k = tid; k < TK; k += 256) {
        float s = 0.f;
        #pragma unroll 8
        for (int c = 0; c < 80; c++) { const float v = Ks[c * TK + k]; s = fmaf(v, v, s); }
        k2s[k] = s;
    }
    __syncthreads();

    const int warp = tid >> 5, lane = tid & 31;
    constexpr int KI = 7;

    float s[4][KI];
    #pragma unroll
    for (int r = 0; r < 4; r++)
        #pragma unroll
        for (int i = 0; i < KI; i++) s[r][i] = 0.f;

    for (int c = 0; c < 80; c++) {
        float qv[4];
        #pragma unroll
        for (int r = 0; r < 4; r++) qv[r] = Qs[(warp * 4 + r) * 81 + c];
        float kv[KI];
        #pragma unroll
        for (int i = 0; i < 6; i++) kv[i] = Ks[c * TK + lane + 32 * i];
        kv[6] = (lane < 8) ? Ks[c * TK + lane + 192] : 0.f;
        #pragma unroll
        for (int r = 0; r < 4; r++)
            #pragma unroll
            for (int i = 0; i < KI; i++)
                s[r][i] = fmaf(qv[r], kv[i], s[r][i]);
    }

    const float NEG_INF = -CUDART_INF_F;
    #pragma unroll
    for (int r = 0; r < 4; r++) {
        const int q = q0 + warp * 4 + r;
        const size_t row = ((size_t)b * TQ + q) * TK;

        float m1 = NEG_INF;
        #pragma unroll
        for (int i = 0; i < KI; i++) {
            const int k = lane + 32 * i;
            const float sc = (k < TK) ? -5e-4f * (k2s[k] - 2.f * s[r][i]) : NEG_INF;
            s[r][i] = sc;
            m1 = fmaxf(m1, sc);
        }
        m1 = warp_max(m1);

        float e[KI];
        float se = 0.f;
        #pragma unroll
        for (int i = 0; i < KI; i++) {
            const int k = lane + 32 * i;
            if (k < TK) { e[i] = __expf(s[r][i] - m1); se += e[i]; }
        }
        se = warp_sum(se);
        const float lse = m1 + __logf(se);

        float se2 = 0.f;
        #pragma unroll
        for (int i = 0; i < KI; i++) {
            const int k = lane + 32 * i;
            if (k < TK) {
                const float pr = prior[row + k] + 1e-8f;
                logp_out[row + k] = s[r][i] - lse + __logf(pr);
                const float wv = mask[b * TK + k] ? 0.f : e[i] * pr;
                e[i] = wv;
                se2 += wv;
            }
        }
        se2 = warp_sum(se2);
        const float inv = 1.f / se2;
        #pragma unroll
        for (int i = 0; i < KI; i++) {
            const int k = lane + 32 * i;
            if (k < TK) attn_out[row + k] = e[i] * inv;
        }
    }
}

// ---------------------------------------------------------------------------
extern "C" void kernel_launch(void* const* d_in, const int* in_sizes, int n_in,
                              void* d_out, int out_size)
{
    const float* queries = (const float*)d_in[0];
    const float* keys    = (const float*)d_in[1];
    const unsigned char* mask = (const unsigned char*)d_in[3];
    const float* prior   = (const float*)d_in[4];
    const float* kW1 = (const float*)d_in[5];
    const float* kb1 = (const float*)d_in[6];
    const float* kW2 = (const float*)d_in[7];
    const float* kb2 = (const float*)d_in[8];
    const float* qW1 = (const float*)d_in[9];
    const float* qb1 = (const float*)d_in[10];
    const float* qW2 = (const float*)d_in[11];
    const float* qb2 = (const float*)d_in[12];
    const float* qW3 = (const float*)d_in[13];
    const float* qb3 = (const float*)d_in[14];

    float* out      = (float*)d_out;
    float* attn_out = out;
    float* logp_out = out + (size_t)BATCH * TQ * TK;

    __nv_bfloat16 *kcol, *qbf, *kW1bf, *kW2bf, *qW1bf, *qW2bf, *qW3bf;
    float *kenc, *qenc;
    cudaGetSymbolAddress((void**)&kcol,  g_kcol);
    cudaGetSymbolAddress((void**)&qbf,   g_qbf);
    cudaGetSymbolAddress((void**)&kW1bf, g_kW1bf);
    cudaGetSymbolAddress((void**)&kW2bf, g_kW2bf);
    cudaGetSymbolAddress((void**)&qW1bf, g_qW1bf);
    cudaGetSymbolAddress((void**)&qW2bf, g_qW2bf);
    cudaGetSymbolAddress((void**)&qW3bf, g_qW3bf);
    cudaGetSymbolAddress((void**)&kenc,  g_kenc);
    cudaGetSymbolAddress((void**)&qenc,  g_qenc);

    static cudaStream_t sB = nullptr;
    static cudaEvent_t evFork = nullptr, evK = nullptr, evJoin = nullptr;
    if (sB == nullptr) {
        cudaStreamCreateWithFlags(&sB, cudaStreamNonBlocking);
        cudaEventCreateWithFlags(&evFork, cudaEventDisableTiming);
        cudaEventCreateWithFlags(&evK,    cudaEventDisableTiming);
        cudaEventCreateWithFlags(&evJoin, cudaEventDisableTiming);
        cudaFuncSetAttribute(im2col_keys, cudaFuncAttributeMaxDynamicSharedMemorySize, IC_SMEM);
        cudaFuncSetAttribute(conv1_fused, cudaFuncAttributeMaxDynamicSharedMemorySize, C1_SMEM);
        cudaFuncSetAttribute(fused_q,     cudaFuncAttributeMaxDynamicSharedMemorySize, QF_SMEM);
        cudaFuncSetAttribute(attn_kernel, cudaFuncAttributeMaxDynamicSharedMemorySize,
                             (80 * TK + 32 * 81 + TK) * (int)sizeof(float));
    }

    // ---- fork: stream B = convert_k (feeds conv1) then query path ----
    cudaEventRecord(evFork, 0);
    cudaStreamWaitEvent(sB, evFork, 0);

    convert_k<<<(CK_TOT / 4 + 255) / 256, 256, 0, sB>>>(kW1, kW2);
    cudaEventRecord(evK, sB);
    convert_q<<<(CQ_TOT / 4 + 255) / 256, 256, 0, sB>>>(queries, qW1, qW2, qW3);
    fused_q<<<BATCH * TQ / 128, 512, QF_SMEM, sB>>>(qbf, qW1bf, qb1, qW2bf, qb2, qW3bf, qb3, qenc);
    cudaEventRecord(evJoin, sB);

    // ---- stream 0: keys path (im2col overlaps convert_k) ----
    im2col_keys<<<BATCH * 8, 256, IC_SMEM>>>(keys);
    init_kenc<<<(BATCH * 80 * TK + 255) / 256, 256>>>(kb2);
    cudaStreamWaitEvent(0, evK, 0);
    conv1_fused<<<dim3(BATCH * TK / 64, 1024 / 128), 256, C1_SMEM>>>(kcol, kW1bf, kb1, kW2bf, kenc);

    // ---- join, then attention ----
    cudaStreamWaitEvent(0, evJoin, 0);
    const int smem = (80 * TK + 32 * 81 + TK) * (int)sizeof(float);
    attn_kernel<<<dim3(TQ / 32, BATCH), 256, smem>>>(qenc, kenc, prior, mask, attn_out, logp_out);
}

// round 11
// speedup vs baseline: 1.1488x; 1.1488x over previous
#include <cuda_runtime.h>
#include <cuda_bf16.h>
#include <math_constants.h>
#include <cstdint>
#include <cstddef>

#define BATCH 16
#define TQ 800
#define TK 200

// ---------------------------------------------------------------------------
// Device-global scratch (no allocations allowed)
// ---------------------------------------------------------------------------
__device__ __align__(16) __nv_bfloat16 g_keysT[BATCH * TK * 512];    // keys transposed [b][t][ci], bf16
__device__ __align__(16) __nv_bfloat16 g_qbf  [BATCH * 80  * TQ];
__device__ __align__(16) __nv_bfloat16 g_kW1bf[1024 * 1536];         // W1 reordered: [co][k'=w*512+ci]
__device__ __align__(16) __nv_bfloat16 g_kW2bf[80 * 1024];
__device__ __align__(16) __nv_bfloat16 g_qW1bf[160 * 240];
__device__ __align__(16) __nv_bfloat16 g_qW2bf[80 * 160];
__device__ __align__(16) __nv_bfloat16 g_qW3bf[80 * 80];
__device__ float g_kenc[BATCH * 80 * TK];
__device__ float g_qenc[BATCH * 80 * TQ];

__device__ __forceinline__ uint32_t smem_to_u32(const void* p) {
    uint32_t a;
    asm("{ .reg .u64 t; cvta.to.shared.u64 t, %1; cvt.u32.u64 %0, t; }" : "=r"(a) : "l"(p));
    return a;
}
__device__ __forceinline__ void ldsm_x4(uint32_t& r0, uint32_t& r1, uint32_t& r2, uint32_t& r3,
                                        uint32_t addr) {
    asm volatile("ldmatrix.sync.aligned.m8n8.x4.shared.b16 {%0,%1,%2,%3}, [%4];"
                 : "=r"(r0), "=r"(r1), "=r"(r2), "=r"(r3) : "r"(addr));
}
__device__ __forceinline__ void mma_bf16(float* c, uint32_t a0, uint32_t a1, uint32_t a2, uint32_t a3,
                                         uint32_t b0, uint32_t b1) {
    asm volatile("mma.sync.aligned.m16n8k16.row.col.f32.bf16.bf16.f32 "
                 "{%0,%1,%2,%3}, {%4,%5,%6,%7}, {%8,%9}, {%0,%1,%2,%3};"
                 : "+f"(c[0]), "+f"(c[1]), "+f"(c[2]), "+f"(c[3])
                 : "r"(a0), "r"(a1), "r"(a2), "r"(a3), "r"(b0), "r"(b1));
}
__device__ __forceinline__ void cp16(uint32_t dst, const void* src) {
    asm volatile("cp.async.ca.shared.global [%0], [%1], 16;" :: "r"(dst), "l"(src));
}
// cp.async with src-size operand: bytes beyond sz are zero-filled (sz=0 -> all zeros)
__device__ __forceinline__ void cp16z(uint32_t dst, const void* src, uint32_t sz) {
    asm volatile("cp.async.ca.shared.global [%0], [%1], 16, %2;" :: "r"(dst), "l"(src), "r"(sz));
}
__device__ __forceinline__ void cp_commit() {
    asm volatile("cp.async.commit_group;" ::: "memory");
}

// ===========================================================================
// keys [b][512][200] f32 -> keysT [b][t][ci] bf16 (tiled transpose)
// grid (8 t-tiles of 25, 4 ci-tiles of 128, 16 b), 256 threads
// ===========================================================================
__global__ __launch_bounds__(256)
void transpose_keys(const float* __restrict__ keys)
{
    __shared__ float ts[128][27];   // [ci][t] (+2 pad)
    const int t0  = blockIdx.x * 25;
    const int ci0 = blockIdx.y * 128;
    const int b   = blockIdx.z;
    const int tid = threadIdx.x;

    for (int idx = tid; idx < 128 * 25; idx += 256) {
        const int ci = idx / 25;
        const int tt = idx - ci * 25;
        ts[ci][tt] = keys[((size_t)b * 512 + ci0 + ci) * TK + t0 + tt];
    }
    __syncthreads();

    for (int idx = tid; idx < 25 * 64; idx += 256) {
        const int tt = idx >> 6;
        const int cp = (idx & 63) << 1;
        __nv_bfloat162 v = __floats2bfloat162_rn(ts[cp][tt], ts[cp + 1][tt]);
        *reinterpret_cast<__nv_bfloat162*>(
            &g_keysT[((size_t)b * TK + t0 + tt) * 512 + ci0 + cp]) = v;
    }
}

// ===========================================================================
// Keys-path weight conversion. W1 is PERMUTED into w-major K order:
//   out[co][w*512+ci] = in[co][ci*3+w]   (bf16)
// ===========================================================================
#define CK_S2 (1024 * 1536)
#define CK_S3 (80 * 1024)
#define CK_TOT (CK_S2 + CK_S3)

__global__ __launch_bounds__(256)
void convert_k(const float* __restrict__ kW1, const float* __restrict__ kW2)
{
    const long e = ((long)blockIdx.x * 256 + threadIdx.x) * 4;
    if (e >= CK_TOT) return;
    if (e < CK_S2) {
        const int co = (int)(e / 1536);
        const int kp = (int)(e - (long)co * 1536);   // k', multiple of 4, same w for all 4
        const int w  = kp >> 9;
        const int ci = kp & 511;
        const float* src = kW1 + (size_t)co * 1536 + ci * 3 + w;
        __nv_bfloat16 v[4];
        #pragma unroll
        for (int i = 0; i < 4; i++) v[i] = __float2bfloat16(src[i * 3]);
        *reinterpret_cast<uint2*>(&g_kW1bf[e]) = *reinterpret_cast<uint2*>(v);
    } else {
        const long off = e - CK_S2;
        const float4 v = *reinterpret_cast<const float4*>(kW2 + off);
        __nv_bfloat162* d2 = reinterpret_cast<__nv_bfloat162*>(g_kW2bf + off);
        d2[0] = __float22bfloat162_rn(make_float2(v.x, v.y));
        d2[1] = __float22bfloat162_rn(make_float2(v.z, v.w));
    }
}

// ===========================================================================
// Query-path conversion (unchanged)
// ===========================================================================
#define CQ_S1 (BATCH * 80 * TQ)
#define CQ_S4 (160 * 240)
#define CQ_S5 (80 * 160)
#define CQ_S6 (80 * 80)
#define CQ_O4 (CQ_S1)
#define CQ_O5 (CQ_O4 + CQ_S4)
#define CQ_O6 (CQ_O5 + CQ_S5)
#define CQ_TOT (CQ_O6 + CQ_S6)

__global__ __launch_bounds__(256)
void convert_q(const float* __restrict__ queries, const float* __restrict__ qW1,
               const float* __restrict__ qW2, const float* __restrict__ qW3)
{
    const long e = ((long)blockIdx.x * 256 + threadIdx.x) * 4;
    if (e >= CQ_TOT) return;
    const float* src; __nv_bfloat16* dst; long off;
    if      (e < CQ_O4) { src = queries; dst = g_qbf;   off = e; }
    else if (e < CQ_O5) { src = qW1;     dst = g_qW1bf; off = e - CQ_O4; }
    else if (e < CQ_O6) { src = qW2;     dst = g_qW2bf; off = e - CQ_O5; }
    else                { src = qW3;     dst = g_qW3bf; off = e - CQ_O6; }
    const float4 v = *reinterpret_cast<const float4*>(src + off);
    __nv_bfloat162* d2 = reinterpret_cast<__nv_bfloat162*>(dst + off);
    d2[0] = __float22bfloat162_rn(make_float2(v.x, v.y));
    d2[1] = __float22bfloat162_rn(make_float2(v.z, v.w));
}

__global__ __launch_bounds__(256)
void init_kenc(const float* __restrict__ kb2)
{
    const int idx = blockIdx.x * 256 + threadIdx.x;
    if (idx < BATCH * 80 * TK)
        g_kenc[idx] = kb2[(idx / TK) % 80];
}

// ===========================================================================
// keys conv1 (512->1024,k3) + fused pointwise conv2.
// K in w-major order: chunk ch -> w = ch/8, ci0 = (ch%8)*64.
// B-operand cp.asyncs DIRECTLY from keysT (no kcol): row n -> keysT[b][t+w-1][ci0..+63],
// zero-filled via src-size=0 at the halo.
// ===========================================================================
#define C1_K   1536
#define C1_LD  72
#define C2_LD  136
#define C1_SMEM 82944

__global__ __launch_bounds__(256)
void conv1_fused(const __nv_bfloat16* __restrict__ keysT, const __nv_bfloat16* __restrict__ W1,
                 const float* __restrict__ bias1, const __nv_bfloat16* __restrict__ W2,
                 float* __restrict__ kenc)
{
    extern __shared__ char dsm[];
    const uint32_t smb = smem_to_u32(dsm);
    const int tid  = threadIdx.x;
    const int wid  = tid >> 5;
    const int lane = tid & 31;
    const int m0 = blockIdx.y * 128;
    const int n0 = blockIdx.x * 64;
    const int warp_m = wid >> 1;
    const int warp_n = wid & 1;

    auto prefetch = [&](int ch, int st) {
        const int k0 = ch * 64;
        const int w  = k0 >> 9;          // 0..2
        const int ci0 = k0 & 511;
        const uint32_t Ab = smb + st * 18432;
        const uint32_t Bb = smb + 55296 + st * 9216;
        #pragma unroll
        for (int j = 0; j < 4; j++) {    // A: 1024 16B chunks (reordered W1, rows contiguous)
            const int e  = tid + 256 * j;
            const int r  = e >> 3;
            const int kq = (e & 7) << 3;
            cp16(Ab + (r * C1_LD + kq) * 2, W1 + (size_t)(m0 + r) * C1_K + k0 + kq);
        }
        #pragma unroll
        for (int j = 0; j < 2; j++) {    // B: 512 16B chunks direct from keysT
            const int e  = tid + 256 * j;
            const int r  = e >> 3;
            const int kq = (e & 7) << 3;
            const int n  = n0 + r;
            const int bb = n / TK;
            const int t  = n - bb * TK;
            const int tg = t + w - 1;
            const bool ok = (tg >= 0) && (tg < TK);
            const int tc = ok ? tg : 0;  // clamped pointer; sz=0 when !ok
            cp16z(Bb + (r * C1_LD + kq) * 2,
                  keysT + ((size_t)bb * TK + tc) * 512 + ci0 + kq,
                  ok ? 16u : 0u);
        }
        cp_commit();
    };

    float acc[2][4][4];
    #pragma unroll
    for (int mt = 0; mt < 2; mt++)
        #pragma unroll
        for (int nt = 0; nt < 4; nt++)
            #pragma unroll
            for (int i = 0; i < 4; i++) acc[mt][nt][i] = 0.f;

    prefetch(0, 0);
    prefetch(1, 1);

    const uint32_t a_lane = ((warp_m * 32 + (lane & 15)) * C1_LD + (lane >> 4) * 8) * 2;
    const uint32_t b_lane = ((warp_n * 32 + (lane & 15)) * C1_LD + (lane >> 4) * 8) * 2;

    for (int ch = 0; ch < 24; ch++) {
        if (ch < 23) asm volatile("cp.async.wait_group 1;" ::: "memory");
        else         asm volatile("cp.async.wait_group 0;" ::: "memory");
        __syncthreads();

        const int st = ch % 3;
        const uint32_t a_addr0 = smb + st * 18432 + a_lane;
        const uint32_t b_addr0 = smb + 55296 + st * 9216 + b_lane;

        #pragma unroll
        for (int ks = 0; ks < 4; ks++) {
            const uint32_t koff = ks * 32;
            uint32_t a[2][4], b[2][4];
            #pragma unroll
            for (int mt = 0; mt < 2; mt++)
                ldsm_x4(a[mt][0], a[mt][1], a[mt][2], a[mt][3],
                        a_addr0 + mt * 16 * C1_LD * 2 + koff);
            #pragma unroll
            for (int np = 0; np < 2; np++)
                ldsm_x4(b[np][0], b[np][1], b[np][2], b[np][3],
                        b_addr0 + np * 16 * C1_LD * 2 + koff);
            #pragma unroll
            for (int mt = 0; mt < 2; mt++)
                #pragma unroll
                for (int np = 0; np < 2; np++) {
                    mma_bf16(acc[mt][np * 2 + 0], a[mt][0], a[mt][1], a[mt][2], a[mt][3],
                             b[np][0], b[np][2]);
                    mma_bf16(acc[mt][np * 2 + 1], a[mt][0], a[mt][1], a[mt][2], a[mt][3],
                             b[np][1], b[np][3]);
                }
        }
        if (ch + 2 < 24) prefetch(ch + 2, (ch + 2) % 3);
    }
    __syncthreads();

    __nv_bfloat16* Sh  = reinterpret_cast<__nv_bfloat16*>(dsm);            // 64n x 136
    __nv_bfloat16* W2s = reinterpret_cast<__nv_bfloat16*>(dsm + 17408);    // 80 x 136

    #pragma unroll
    for (int mt = 0; mt < 2; mt++) {
        const int col = warp_m * 32 + mt * 16 + (lane >> 2);
        const float bv0 = bias1[m0 + col];
        const float bv1 = bias1[m0 + col + 8];
        #pragma unroll
        for (int nt = 0; nt < 4; nt++) {
            const int nb = warp_n * 32 + (nt >> 1) * 16 + (nt & 1) * 8 + ((lane & 3) << 1);
            #pragma unroll
            for (int cc = 0; cc < 2; cc++) {
                Sh[(nb + cc) * C2_LD + col]     = __float2bfloat16(fmaxf(acc[mt][nt][cc]     + bv0, 0.f));
                Sh[(nb + cc) * C2_LD + col + 8] = __float2bfloat16(fmaxf(acc[mt][nt][2 + cc] + bv1, 0.f));
            }
        }
    }
    for (int e = tid; e < 80 * 32; e += 256) {
        const int r = e >> 5;
        const int q = (e & 31) << 2;
        *reinterpret_cast<uint2*>(&W2s[r * C2_LD + q]) =
            *reinterpret_cast<const uint2*>(W2 + (size_t)r * 1024 + m0 + q);
    }
    __syncthreads();

    if (wid < 4) {
        const uint32_t sh_addr = smem_to_u32(Sh)  + ((wid * 16 + (lane & 15)) * C2_LD + (lane >> 4) * 8) * 2;
        const uint32_t w2_addr = smem_to_u32(W2s) + ((lane & 15) * C2_LD + (lane >> 4) * 8) * 2;
        float acc2[5][2][4];
        #pragma unroll
        for (int ct = 0; ct < 5; ct++)
            #pragma unroll
            for (int s = 0; s < 2; s++)
                #pragma unroll
                for (int i = 0; i < 4; i++) acc2[ct][s][i] = 0.f;

        #pragma unroll
        for (int ks = 0; ks < 8; ks++) {
            const uint32_t koff = ks * 32;
            uint32_t a0, a1, a2, a3;
            ldsm_x4(a0, a1, a2, a3, sh_addr + koff);
            #pragma unroll
            for (int ct = 0; ct < 5; ct++) {
                uint32_t b0, b1, b2, b3;
                ldsm_x4(b0, b1, b2, b3, w2_addr + ct * 16 * C2_LD * 2 + koff);
                mma_bf16(acc2[ct][0], a0, a1, a2, a3, b0, b2);
                mma_bf16(acc2[ct][1], a0, a1, a2, a3, b1, b3);
            }
        }
        #pragma unroll
        for (int ct = 0; ct < 5; ct++)
            #pragma unroll
            for (int s = 0; s < 2; s++)
                #pragma unroll
                for (int i = 0; i < 4; i++) {
                    const int co2 = ct * 16 + s * 8 + ((lane & 3) << 1) + (i & 1);
                    const int n   = n0 + wid * 16 + (lane >> 2) + ((i >> 1) << 3);
                    const int bb  = n / TK;
                    const int t   = n - bb * TK;
                    atomicAdd(kenc + ((size_t)bb * 80 + co2) * TK + t, acc2[ct][s][i]);
                }
    }
}

// ===========================================================================
// FUSED query path, 512 threads (R8 version — best measured).
// ===========================================================================
#define QF_SMEM 185856

__global__ __launch_bounds__(512)
void fused_q(const __nv_bfloat16* __restrict__ qbf,
             const __nv_bfloat16* __restrict__ W1, const float* __restrict__ b1,
             const __nv_bfloat16* __restrict__ W2, const float* __restrict__ b2,
             const __nv_bfloat16* __restrict__ W3, const float* __restrict__ b3,
             float* __restrict__ qenc)
{
    extern __shared__ char dsm[];
    __nv_bfloat16* A1  = reinterpret_cast<__nv_bfloat16*>(dsm);
    __nv_bfloat16* W1s = reinterpret_cast<__nv_bfloat16*>(dsm + 63488);
    __nv_bfloat16* H1  = reinterpret_cast<__nv_bfloat16*>(dsm + 142848);
    __nv_bfloat16* W2s = reinterpret_cast<__nv_bfloat16*>(dsm);
    __nv_bfloat16* H2  = reinterpret_cast<__nv_bfloat16*>(dsm + 26880);
    __nv_bfloat16* W3s = reinterpret_cast<__nv_bfloat16*>(dsm + 49408);

    const int tid  = threadIdx.x;
    const int wid  = tid >> 5;
    const int lane = tid & 31;
    const int n0   = blockIdx.x * 128;
    const int rowq = (lane & 15);
    const int kq8  = (lane >> 4) * 8;

    #pragma unroll
    for (int j = 0; j < 15; j++) {
        const int kl = (tid >> 5) + j * 16;
        const int ci = kl / 3;
        const int w  = kl - ci * 3;
        #pragma unroll
        for (int i = 0; i < 4; i++) {
            const int r  = ((tid & 31) << 2) + i;
            const int n  = n0 + r;
            const int bb = n / TQ;
            const int t  = n - bb * TQ;
            const int tg = t + w - 1;
            __nv_bfloat16 v = __float2bfloat16(0.f);
            if (tg >= 0 && tg < TQ) v = qbf[((size_t)bb * 80 + ci) * TQ + tg];
            A1[r * 248 + kl] = v;
        }
    }
    for (int e = tid; e < 160 * 60; e += 512) {
        const int r = e / 60;
        const int q = (e - r * 60) * 4;
        *reinterpret_cast<uint2*>(&W1s[r * 248 + q]) =
            *reinterpret_cast<const uint2*>(W1 + (size_t)r * 240 + q);
    }
    __syncthreads();

    {
        const int ng  = wid & 7;
        const int coh = (wid >> 3) * 80;
        const uint32_t a_addr = smem_to_u32(A1)  + ((ng * 16 + rowq) * 248 + kq8) * 2;
        const uint32_t b_addr = smem_to_u32(W1s) + ((coh + rowq) * 248 + kq8) * 2;
        float acc1[5][2][4];
        #pragma unroll
        for (int ct = 0; ct < 5; ct++)
            #pragma unroll
            for (int s = 0; s < 2; s++)
                #pragma unroll
                for (int i = 0; i < 4; i++) acc1[ct][s][i] = 0.f;
        #pragma unroll
        for (int ks = 0; ks < 15; ks++) {
            const uint32_t koff = ks * 32;
            uint32_t a0, a1, a2, a3;
            ldsm_x4(a0, a1, a2, a3, a_addr + koff);
            #pragma unroll
            for (int ct = 0; ct < 5; ct++) {
                uint32_t b0, b1, b2, b3;
                ldsm_x4(b0, b1, b2, b3, b_addr + ct * 16 * 248 * 2 + koff);
                mma_bf16(acc1[ct][0], a0, a1, a2, a3, b0, b2);
                mma_bf16(acc1[ct][1], a0, a1, a2, a3, b1, b3);
            }
        }
        __syncthreads();
        #pragma unroll
        for (int ct = 0; ct < 5; ct++)
            #pragma unroll
            for (int s = 0; s < 2; s++)
                #pragma unroll
                for (int i = 0; i < 4; i++) {
                    const int co = coh + ct * 16 + s * 8 + ((lane & 3) << 1) + (i & 1);
                    const int nl = ng * 16 + (lane >> 2) + ((i >> 1) << 3);
                    H1[nl * 168 + co] = __float2bfloat16(fmaxf(acc1[ct][s][i] + b1[co], 0.f));
                }
    }
    for (int e = tid; e < 80 * 40; e += 512) {
        const int r = e / 40;
        const int q = (e - r * 40) * 4;
        *reinterpret_cast<uint2*>(&W2s[r * 168 + q]) =
            *reinterpret_cast<const uint2*>(W2 + (size_t)r * 160 + q);
    }
    __syncthreads();

    if (wid >= 8) {
        for (int e = tid - 256; e < 80 * 20; e += 256) {
            const int r = e / 20;
            const int q = (e - r * 20) * 4;
            *reinterpret_cast<uint2*>(&W3s[r * 88 + q]) =
                *reinterpret_cast<const uint2*>(W3 + (size_t)r * 80 + q);
        }
    } else {
        const uint32_t a_addr = smem_to_u32(H1)  + ((wid * 16 + rowq) * 168 + kq8) * 2;
        const uint32_t b_addr = smem_to_u32(W2s) + (rowq * 168 + kq8) * 2;
        float acc2[5][2][4];
        #pragma unroll
        for (int ct = 0; ct < 5; ct++)
            #pragma unroll
            for (int s = 0; s < 2; s++)
                #pragma unroll
                for (int i = 0; i < 4; i++) acc2[ct][s][i] = 0.f;
        #pragma unroll
        for (int ks = 0; ks < 10; ks++) {
            const uint32_t koff = ks * 32;
            uint32_t a0, a1, a2, a3;
            ldsm_x4(a0, a1, a2, a3, a_addr + koff);
            #pragma unroll
            for (int ct = 0; ct < 5; ct++) {
                uint32_t b0, b1, b2, b3;
                ldsm_x4(b0, b1, b2, b3, b_addr + ct * 16 * 168 * 2 + koff);
                mma_bf16(acc2[ct][0], a0, a1, a2, a3, b0, b2);
                mma_bf16(acc2[ct][1], a0, a1, a2, a3, b1, b3);
            }
        }
        #pragma unroll
        for (int ct = 0; ct < 5; ct++)
            #pragma unroll
            for (int s = 0; s < 2; s++)
                #pragma unroll
                for (int i = 0; i < 4; i++) {
                    const int co = ct * 16 + s * 8 + ((lane & 3) << 1) + (i & 1);
                    const int nl = wid * 16 + (lane >> 2) + ((i >> 1) << 3);
                    H2[nl * 88 + co] = __float2bfloat16(fmaxf(acc2[ct][s][i] + b2[co], 0.f));
                }
    }
    __syncthreads();

    if (wid < 8) {
        const uint32_t a_addr = smem_to_u32(H2)  + ((wid * 16 + rowq) * 88 + kq8) * 2;
        const uint32_t b_addr = smem_to_u32(W3s) + (rowq * 88 + kq8) * 2;
        float acc3[5][2][4];
        #pragma unroll
        for (int ct = 0; ct < 5; ct++)
            #pragma unroll
            for (int s = 0; s < 2; s++)
                #pragma unroll
                for (int i = 0; i < 4; i++) acc3[ct][s][i] = 0.f;
        #pragma unroll
        for (int ks = 0; ks < 5; ks++) {
            const uint32_t koff = ks * 32;
            uint32_t a0, a1, a2, a3;
            ldsm_x4(a0, a1, a2, a3, a_addr + koff);
            #pragma unroll
            for (int ct = 0; ct < 5; ct++) {
                uint32_t b0, b1, b2, b3;
                ldsm_x4(b0, b1, b2, b3, b_addr + ct * 16 * 88 * 2 + koff);
                mma_bf16(acc3[ct][0], a0, a1, a2, a3, b0, b2);
                mma_bf16(acc3[ct][1], a0, a1, a2, a3, b1, b3);
            }
        }
        #pragma unroll
        for (int ct = 0; ct < 5; ct++)
            #pragma unroll
            for (int s = 0; s < 2; s++)
                #pragma unroll
                for (int i = 0; i < 4; i++) {
                    const int co = ct * 16 + s * 8 + ((lane & 3) << 1) + (i & 1);
                    const int n  = n0 + wid * 16 + (lane >> 2) + ((i >> 1) << 3);
                    const int bb = n / TQ;
                    const int t  = n - bb * TQ;
                    qenc[((size_t)bb * 80 + co) * TQ + t] = acc3[ct][s][i] + b3[co];
                }
    }
}

// ---------------------------------------------------------------------------
// Fused attention (R8 version)
// ---------------------------------------------------------------------------
static __device__ __forceinline__ float warp_max(float v) {
    #pragma unroll
    for (int o = 16; o > 0; o >>= 1) v = fmaxf(v, __shfl_xor_sync(0xffffffffu, v, o));
    return v;
}
static __device__ __forceinline__ float warp_sum(float v) {
    #pragma unroll
    for (int o = 16; o > 0; o >>= 1) v += __shfl_xor_sync(0xffffffffu, v, o);
    return v;
}

__global__ __launch_bounds__(256)
void attn_kernel(const float* __restrict__ qenc, const float* __restrict__ kenc,
                 const float* __restrict__ prior, const unsigned char* __restrict__ mask,
                 float* __restrict__ attn_out, float* __restrict__ logp_out)
{
    extern __shared__ float sm[];
    float* Ks  = sm;
    float* Qs  = sm + 80 * TK;
    float* k2s = Qs + 32 * 81;

    const int b   = blockIdx.y;
    const int q0  = blockIdx.x * 32;
    const int tid = threadIdx.x;

    const float* kb = kenc + (size_t)b * 80 * TK;
    for (int i = tid; i < 80 * TK / 4; i += 256)
        reinterpret_cast<float4*>(Ks)[i] = reinterpret_cast<const float4*>(kb)[i];

    const float* qb = qenc + (size_t)b * 80 * TQ;
    {
        const int ql = tid & 31;
        for (int c = tid >> 5; c < 80; c += 8)
            Qs[ql * 81 + c] = qb[c * TQ + q0 + ql];
    }
    __syncthreads();

    for (int k = tid; k < TK; k += 256) {
        float s = 0.f;
        #pragma unroll 8
        for (int c = 0; c < 80; c++) { const float v = Ks[c * TK + k]; s = fmaf(v, v, s); }
        k2s[k] = s;
    }
    __syncthreads();

    const int warp = tid >> 5, lane = tid & 31;
    constexpr int KI = 7;

    float s[4][KI];
    #pragma unroll
    for (int r = 0; r < 4; r++)
        #pragma unroll
        for (int i = 0; i < KI; i++) s[r][i] = 0.f;

    for (int c = 0; c < 80; c++) {
        float qv[4];
        #pragma unroll
        for (int r = 0; r < 4; r++) qv[r] = Qs[(warp * 4 + r) * 81 + c];
        float kv[KI];
        #pragma unroll
        for (int i = 0; i < 6; i++) kv[i] = Ks[c * TK + lane + 32 * i];
        kv[6] = (lane < 8) ? Ks[c * TK + lane + 192] : 0.f;
        #pragma unroll
        for (int r = 0; r < 4; r++)
            #pragma unroll
            for (int i = 0; i < KI; i++)
                s[r][i] = fmaf(qv[r], kv[i], s[r][i]);
    }

    const float NEG_INF = -CUDART_INF_F;
    #pragma unroll
    for (int r = 0; r < 4; r++) {
        const int q = q0 + warp * 4 + r;
        const size_t row = ((size_t)b * TQ + q) * TK;

        float m1 = NEG_INF;
        #pragma unroll
        for (int i = 0; i < KI; i++) {
            const int k = lane + 32 * i;
            const float sc = (k < TK) ? -5e-4f * (k2s[k] - 2.f * s[r][i]) : NEG_INF;
            s[r][i] = sc;
            m1 = fmaxf(m1, sc);
        }
        m1 = warp_max(m1);

        float e[KI];
        float se = 0.f;
        #pragma unroll
        for (int i = 0; i < KI; i++) {
            const int k = lane + 32 * i;
            if (k < TK) { e[i] = __expf(s[r][i] - m1); se += e[i]; }
        }
        se = warp_sum(se);
        const float lse = m1 + __logf(se);

        float se2 = 0.f;
        #pragma unroll
        for (int i = 0; i < KI; i++) {
            const int k = lane + 32 * i;
            if (k < TK) {
                const float pr = prior[row + k] + 1e-8f;
                logp_out[row + k] = s[r][i] - lse + __logf(pr);
                const float wv = mask[b * TK + k] ? 0.f : e[i] * pr;
                e[i] = wv;
                se2 += wv;
            }
        }
        se2 = warp_sum(se2);
        const float inv = 1.f / se2;
        #pragma unroll
        for (int i = 0; i < KI; i++) {
            const int k = lane + 32 * i;
            if (k < TK) attn_out[row + k] = e[i] * inv;
        }
    }
}

// ---------------------------------------------------------------------------
extern "C" void kernel_launch(void* const* d_in, const int* in_sizes, int n_in,
                              void* d_out, int out_size)
{
    const float* queries = (const float*)d_in[0];
    const float* keys    = (const float*)d_in[1];
    const unsigned char* mask = (const unsigned char*)d_in[3];
    const float* prior   = (const float*)d_in[4];
    const float* kW1 = (const float*)d_in[5];
    const float* kb1 = (const float*)d_in[6];
    const float* kW2 = (const float*)d_in[7];
    const float* kb2 = (const float*)d_in[8];
    const float* qW1 = (const float*)d_in[9];
    const float* qb1 = (const float*)d_in[10];
    const float* qW2 = (const float*)d_in[11];
    const float* qb2 = (const float*)d_in[12];
    const float* qW3 = (const float*)d_in[13];
    const float* qb3 = (const float*)d_in[14];

    float* out      = (float*)d_out;
    float* attn_out = out;
    float* logp_out = out + (size_t)BATCH * TQ * TK;

    __nv_bfloat16 *keysT, *qbf, *kW1bf, *kW2bf, *qW1bf, *qW2bf, *qW3bf;
    float *kenc, *qenc;
    cudaGetSymbolAddress((void**)&keysT, g_keysT);
    cudaGetSymbolAddress((void**)&qbf,   g_qbf);
    cudaGetSymbolAddress((void**)&kW1bf, g_kW1bf);
    cudaGetSymbolAddress((void**)&kW2bf, g_kW2bf);
    cudaGetSymbolAddress((void**)&qW1bf, g_qW1bf);
    cudaGetSymbolAddress((void**)&qW2bf, g_qW2bf);
    cudaGetSymbolAddress((void**)&qW3bf, g_qW3bf);
    cudaGetSymbolAddress((void**)&kenc,  g_kenc);
    cudaGetSymbolAddress((void**)&qenc,  g_qenc);

    static cudaStream_t sB = nullptr;
    static cudaEvent_t evFork = nullptr, evK = nullptr, evJoin = nullptr;
    if (sB == nullptr) {
        cudaStreamCreateWithFlags(&sB, cudaStreamNonBlocking);
        cudaEventCreateWithFlags(&evFork, cudaEventDisableTiming);
        cudaEventCreateWithFlags(&evK,    cudaEventDisableTiming);
        cudaEventCreateWithFlags(&evJoin, cudaEventDisableTiming);
        cudaFuncSetAttribute(conv1_fused, cudaFuncAttributeMaxDynamicSharedMemorySize, C1_SMEM);
        cudaFuncSetAttribute(fused_q,     cudaFuncAttributeMaxDynamicSharedMemorySize, QF_SMEM);
        cudaFuncSetAttribute(attn_kernel, cudaFuncAttributeMaxDynamicSharedMemorySize,
                             (80 * TK + 32 * 81 + TK) * (int)sizeof(float));
    }

    // ---- fork: stream B = convert_k (feeds conv1) then query path ----
    cudaEventRecord(evFork, 0);
    cudaStreamWaitEvent(sB, evFork, 0);

    convert_k<<<(CK_TOT / 4 + 255) / 256, 256, 0, sB>>>(kW1, kW2);
    cudaEventRecord(evK, sB);
    convert_q<<<(CQ_TOT / 4 + 255) / 256, 256, 0, sB>>>(queries, qW1, qW2, qW3);
    fused_q<<<BATCH * TQ / 128, 512, QF_SMEM, sB>>>(qbf, qW1bf, qb1, qW2bf, qb2, qW3bf, qb3, qenc);
    cudaEventRecord(evJoin, sB);

    // ---- stream 0: keys path (transpose overlaps convert_k) ----
    transpose_keys<<<dim3(8, 4, BATCH), 256>>>(keys);
    init_kenc<<<(BATCH * 80 * TK + 255) / 256, 256>>>(kb2);
    cudaStreamWaitEvent(0, evK, 0);
    conv1_fused<<<dim3(BATCH * TK / 64, 1024 / 128), 256, C1_SMEM>>>(keysT, kW1bf, kb1, kW2bf, kenc);

    // ---- join, then attention ----
    cudaStreamWaitEvent(0, evJoin, 0);
    const int smem = (80 * TK + 32 * 81 + TK) * (int)sizeof(float);
    attn_kernel<<<dim3(TQ / 32, BATCH), 256, smem>>>(qenc, kenc, prior, mask, attn_out, logp_out);
}

// round 12
// speedup vs baseline: 1.1731x; 1.0211x over previous
#include <cuda_runtime.h>
#include <cuda_bf16.h>
#include <math_constants.h>
#include <cstdint>
#include <cstddef>

#define BATCH 16
#define TQ 800
#define TK 200

// ---------------------------------------------------------------------------
// Device-global scratch (no allocations allowed)
// ---------------------------------------------------------------------------
__device__ __align__(16) __nv_bfloat16 g_keysT[BATCH * TK * 512];    // keys transposed [b][t][ci], bf16
__device__ __align__(16) __nv_bfloat16 g_qbf  [BATCH * 80  * TQ];
__device__ __align__(16) __nv_bfloat16 g_kW1bf[1024 * 1536];         // W1 reordered: [co][k'=w*512+ci]
__device__ __align__(16) __nv_bfloat16 g_kW2bf[80 * 1024];
__device__ __align__(16) __nv_bfloat16 g_qW1bf[160 * 240];
__device__ __align__(16) __nv_bfloat16 g_qW2bf[80 * 160];
__device__ __align__(16) __nv_bfloat16 g_qW3bf[80 * 80];
__device__ float g_kenc[BATCH * 80 * TK];
__device__ float g_qenc[BATCH * 80 * TQ];

__device__ __forceinline__ uint32_t smem_to_u32(const void* p) {
    uint32_t a;
    asm("{ .reg .u64 t; cvta.to.shared.u64 t, %1; cvt.u32.u64 %0, t; }" : "=r"(a) : "l"(p));
    return a;
}
__device__ __forceinline__ void ldsm_x4(uint32_t& r0, uint32_t& r1, uint32_t& r2, uint32_t& r3,
                                        uint32_t addr) {
    asm volatile("ldmatrix.sync.aligned.m8n8.x4.shared.b16 {%0,%1,%2,%3}, [%4];"
                 : "=r"(r0), "=r"(r1), "=r"(r2), "=r"(r3) : "r"(addr));
}
__device__ __forceinline__ void mma_bf16(float* c, uint32_t a0, uint32_t a1, uint32_t a2, uint32_t a3,
                                         uint32_t b0, uint32_t b1) {
    asm volatile("mma.sync.aligned.m16n8k16.row.col.f32.bf16.bf16.f32 "
                 "{%0,%1,%2,%3}, {%4,%5,%6,%7}, {%8,%9}, {%0,%1,%2,%3};"
                 : "+f"(c[0]), "+f"(c[1]), "+f"(c[2]), "+f"(c[3])
                 : "r"(a0), "r"(a1), "r"(a2), "r"(a3), "r"(b0), "r"(b1));
}
__device__ __forceinline__ void cp16(uint32_t dst, const void* src) {
    asm volatile("cp.async.ca.shared.global [%0], [%1], 16;" :: "r"(dst), "l"(src));
}
__device__ __forceinline__ void cp16z(uint32_t dst, const void* src, uint32_t sz) {
    asm volatile("cp.async.ca.shared.global [%0], [%1], 16, %2;" :: "r"(dst), "l"(src), "r"(sz));
}
__device__ __forceinline__ void cp_commit() {
    asm volatile("cp.async.commit_group;" ::: "memory");
}

// ===========================================================================
// keys [b][512][200] f32 -> keysT [b][t][ci] bf16 (tiled transpose, v2)
// grid (4 t-tiles of 50, 4 ci-tiles of 128, 16 b) = 256 blocks, 256 threads
// ===========================================================================
__global__ __launch_bounds__(256)
void transpose_keys(const float* __restrict__ keys)
{
    __shared__ float ts[128][52];   // [ci][t] (+2 pad)
    const int t0  = blockIdx.x * 50;
    const int ci0 = blockIdx.y * 128;
    const int b   = blockIdx.z;
    const int tid = threadIdx.x;

    // phase 1: 128 rows x 50 floats, float2 loads (25 per row, contiguous runs)
    for (int idx = tid; idx < 128 * 25; idx += 256) {
        const int ci = idx / 25;
        const int t2 = (idx - ci * 25) * 2;
        const float2 v = *reinterpret_cast<const float2*>(
            keys + ((size_t)b * 512 + ci0 + ci) * TK + t0 + t2);
        ts[ci][t2]     = v.x;
        ts[ci][t2 + 1] = v.y;
    }
    __syncthreads();

    // phase 2: 50 t-rows x 128 ci, bf16x2 writes (contiguous 256B runs)
    for (int idx = tid; idx < 50 * 64; idx += 256) {
        const int tt = idx >> 6;
        const int cp = (idx & 63) << 1;
        __nv_bfloat162 v = __floats2bfloat162_rn(ts[cp][tt], ts[cp + 1][tt]);
        *reinterpret_cast<__nv_bfloat162*>(
            &g_keysT[((size_t)b * TK + t0 + tt) * 512 + ci0 + cp]) = v;
    }
}

// ===========================================================================
// Keys-path weight conversion. W1 permuted into w-major K order.
// ===========================================================================
#define CK_S2 (1024 * 1536)
#define CK_S3 (80 * 1024)
#define CK_TOT (CK_S2 + CK_S3)

__global__ __launch_bounds__(256)
void convert_k(const float* __restrict__ kW1, const float* __restrict__ kW2)
{
    const long e = ((long)blockIdx.x * 256 + threadIdx.x) * 4;
    if (e >= CK_TOT) return;
    if (e < CK_S2) {
        const int co = (int)(e / 1536);
        const int kp = (int)(e - (long)co * 1536);
        const int w  = kp >> 9;
        const int ci = kp & 511;
        const float* src = kW1 + (size_t)co * 1536 + ci * 3 + w;
        __nv_bfloat16 v[4];
        #pragma unroll
        for (int i = 0; i < 4; i++) v[i] = __float2bfloat16(src[i * 3]);
        *reinterpret_cast<uint2*>(&g_kW1bf[e]) = *reinterpret_cast<uint2*>(v);
    } else {
        const long off = e - CK_S2;
        const float4 v = *reinterpret_cast<const float4*>(kW2 + off);
        __nv_bfloat162* d2 = reinterpret_cast<__nv_bfloat162*>(g_kW2bf + off);
        d2[0] = __float22bfloat162_rn(make_float2(v.x, v.y));
        d2[1] = __float22bfloat162_rn(make_float2(v.z, v.w));
    }
}

// ===========================================================================
// Query-path conversion
// ===========================================================================
#define CQ_S1 (BATCH * 80 * TQ)
#define CQ_S4 (160 * 240)
#define CQ_S5 (80 * 160)
#define CQ_S6 (80 * 80)
#define CQ_O4 (CQ_S1)
#define CQ_O5 (CQ_O4 + CQ_S4)
#define CQ_O6 (CQ_O5 + CQ_S5)
#define CQ_TOT (CQ_O6 + CQ_S6)

__global__ __launch_bounds__(256)
void convert_q(const float* __restrict__ queries, const float* __restrict__ qW1,
               const float* __restrict__ qW2, const float* __restrict__ qW3)
{
    const long e = ((long)blockIdx.x * 256 + threadIdx.x) * 4;
    if (e >= CQ_TOT) return;
    const float* src; __nv_bfloat16* dst; long off;
    if      (e < CQ_O4) { src = queries; dst = g_qbf;   off = e; }
    else if (e < CQ_O5) { src = qW1;     dst = g_qW1bf; off = e - CQ_O4; }
    else if (e < CQ_O6) { src = qW2;     dst = g_qW2bf; off = e - CQ_O5; }
    else                { src = qW3;     dst = g_qW3bf; off = e - CQ_O6; }
    const float4 v = *reinterpret_cast<const float4*>(src + off);
    __nv_bfloat162* d2 = reinterpret_cast<__nv_bfloat162*>(dst + off);
    d2[0] = __float22bfloat162_rn(make_float2(v.x, v.y));
    d2[1] = __float22bfloat162_rn(make_float2(v.z, v.w));
}

__global__ __launch_bounds__(256)
void init_kenc(const float* __restrict__ kb2)
{
    const int idx = blockIdx.x * 256 + threadIdx.x;
    if (idx < BATCH * 80 * TK)
        g_kenc[idx] = kb2[(idx / TK) % 80];
}

// ===========================================================================
// keys conv1 (512->1024,k3) + fused pointwise conv2 (unchanged from R11)
// ===========================================================================
#define C1_K   1536
#define C1_LD  72
#define C2_LD  136
#define C1_SMEM 82944

__global__ __launch_bounds__(256)
void conv1_fused(const __nv_bfloat16* __restrict__ keysT, const __nv_bfloat16* __restrict__ W1,
                 const float* __restrict__ bias1, const __nv_bfloat16* __restrict__ W2,
                 float* __restrict__ kenc)
{
    extern __shared__ char dsm[];
    const uint32_t smb = smem_to_u32(dsm);
    const int tid  = threadIdx.x;
    const int wid  = tid >> 5;
    const int lane = tid & 31;
    const int m0 = blockIdx.y * 128;
    const int n0 = blockIdx.x * 64;
    const int warp_m = wid >> 1;
    const int warp_n = wid & 1;

    auto prefetch = [&](int ch, int st) {
        const int k0 = ch * 64;
        const int w  = k0 >> 9;
        const int ci0 = k0 & 511;
        const uint32_t Ab = smb + st * 18432;
        const uint32_t Bb = smb + 55296 + st * 9216;
        #pragma unroll
        for (int j = 0; j < 4; j++) {
            const int e  = tid + 256 * j;
            const int r  = e >> 3;
            const int kq = (e & 7) << 3;
            cp16(Ab + (r * C1_LD + kq) * 2, W1 + (size_t)(m0 + r) * C1_K + k0 + kq);
        }
        #pragma unroll
        for (int j = 0; j < 2; j++) {
            const int e  = tid + 256 * j;
            const int r  = e >> 3;
            const int kq = (e & 7) << 3;
            const int n  = n0 + r;
            const int bb = n / TK;
            const int t  = n - bb * TK;
            const int tg = t + w - 1;
            const bool ok = (tg >= 0) && (tg < TK);
            const int tc = ok ? tg : 0;
            cp16z(Bb + (r * C1_LD + kq) * 2,
                  keysT + ((size_t)bb * TK + tc) * 512 + ci0 + kq,
                  ok ? 16u : 0u);
        }
        cp_commit();
    };

    float acc[2][4][4];
    #pragma unroll
    for (int mt = 0; mt < 2; mt++)
        #pragma unroll
        for (int nt = 0; nt < 4; nt++)
            #pragma unroll
            for (int i = 0; i < 4; i++) acc[mt][nt][i] = 0.f;

    prefetch(0, 0);
    prefetch(1, 1);

    const uint32_t a_lane = ((warp_m * 32 + (lane & 15)) * C1_LD + (lane >> 4) * 8) * 2;
    const uint32_t b_lane = ((warp_n * 32 + (lane & 15)) * C1_LD + (lane >> 4) * 8) * 2;

    for (int ch = 0; ch < 24; ch++) {
        if (ch < 23) asm volatile("cp.async.wait_group 1;" ::: "memory");
        else         asm volatile("cp.async.wait_group 0;" ::: "memory");
        __syncthreads();

        const int st = ch % 3;
        const uint32_t a_addr0 = smb + st * 18432 + a_lane;
        const uint32_t b_addr0 = smb + 55296 + st * 9216 + b_lane;

        #pragma unroll
        for (int ks = 0; ks < 4; ks++) {
            const uint32_t koff = ks * 32;
            uint32_t a[2][4], b[2][4];
            #pragma unroll
            for (int mt = 0; mt < 2; mt++)
                ldsm_x4(a[mt][0], a[mt][1], a[mt][2], a[mt][3],
                        a_addr0 + mt * 16 * C1_LD * 2 + koff);
            #pragma unroll
            for (int np = 0; np < 2; np++)
                ldsm_x4(b[np][0], b[np][1], b[np][2], b[np][3],
                        b_addr0 + np * 16 * C1_LD * 2 + koff);
            #pragma unroll
            for (int mt = 0; mt < 2; mt++)
                #pragma unroll
                for (int np = 0; np < 2; np++) {
                    mma_bf16(acc[mt][np * 2 + 0], a[mt][0], a[mt][1], a[mt][2], a[mt][3],
                             b[np][0], b[np][2]);
                    mma_bf16(acc[mt][np * 2 + 1], a[mt][0], a[mt][1], a[mt][2], a[mt][3],
                             b[np][1], b[np][3]);
                }
        }
        if (ch + 2 < 24) prefetch(ch + 2, (ch + 2) % 3);
    }
    __syncthreads();

    __nv_bfloat16* Sh  = reinterpret_cast<__nv_bfloat16*>(dsm);
    __nv_bfloat16* W2s = reinterpret_cast<__nv_bfloat16*>(dsm + 17408);

    #pragma unroll
    for (int mt = 0; mt < 2; mt++) {
        const int col = warp_m * 32 + mt * 16 + (lane >> 2);
        const float bv0 = bias1[m0 + col];
        const float bv1 = bias1[m0 + col + 8];
        #pragma unroll
        for (int nt = 0; nt < 4; nt++) {
            const int nb = warp_n * 32 + (nt >> 1) * 16 + (nt & 1) * 8 + ((lane & 3) << 1);
            #pragma unroll
            for (int cc = 0; cc < 2; cc++) {
                Sh[(nb + cc) * C2_LD + col]     = __float2bfloat16(fmaxf(acc[mt][nt][cc]     + bv0, 0.f));
                Sh[(nb + cc) * C2_LD + col + 8] = __float2bfloat16(fmaxf(acc[mt][nt][2 + cc] + bv1, 0.f));
            }
        }
    }
    for (int e = tid; e < 80 * 32; e += 256) {
        const int r = e >> 5;
        const int q = (e & 31) << 2;
        *reinterpret_cast<uint2*>(&W2s[r * C2_LD + q]) =
            *reinterpret_cast<const uint2*>(W2 + (size_t)r * 1024 + m0 + q);
    }
    __syncthreads();

    if (wid < 4) {
        const uint32_t sh_addr = smem_to_u32(Sh)  + ((wid * 16 + (lane & 15)) * C2_LD + (lane >> 4) * 8) * 2;
        const uint32_t w2_addr = smem_to_u32(W2s) + ((lane & 15) * C2_LD + (lane >> 4) * 8) * 2;
        float acc2[5][2][4];
        #pragma unroll
        for (int ct = 0; ct < 5; ct++)
            #pragma unroll
            for (int s = 0; s < 2; s++)
                #pragma unroll
                for (int i = 0; i < 4; i++) acc2[ct][s][i] = 0.f;

        #pragma unroll
        for (int ks = 0; ks < 8; ks++) {
            const uint32_t koff = ks * 32;
            uint32_t a0, a1, a2, a3;
            ldsm_x4(a0, a1, a2, a3, sh_addr + koff);
            #pragma unroll
            for (int ct = 0; ct < 5; ct++) {
                uint32_t b0, b1, b2, b3;
                ldsm_x4(b0, b1, b2, b3, w2_addr + ct * 16 * C2_LD * 2 + koff);
                mma_bf16(acc2[ct][0], a0, a1, a2, a3, b0, b2);
                mma_bf16(acc2[ct][1], a0, a1, a2, a3, b1, b3);
            }
        }
        #pragma unroll
        for (int ct = 0; ct < 5; ct++)
            #pragma unroll
            for (int s = 0; s < 2; s++)
                #pragma unroll
                for (int i = 0; i < 4; i++) {
                    const int co2 = ct * 16 + s * 8 + ((lane & 3) << 1) + (i & 1);
                    const int n   = n0 + wid * 16 + (lane >> 2) + ((i >> 1) << 3);
                    const int bb  = n / TK;
                    const int t   = n - bb * TK;
                    atomicAdd(kenc + ((size_t)bb * 80 + co2) * TK + t, acc2[ct][s][i]);
                }
    }
}

// ===========================================================================
// FUSED query path, 512 threads (R8 version — best measured).
// ===========================================================================
#define QF_SMEM 185856

__global__ __launch_bounds__(512)
void fused_q(const __nv_bfloat16* __restrict__ qbf,
             const __nv_bfloat16* __restrict__ W1, const float* __restrict__ b1,
             const __nv_bfloat16* __restrict__ W2, const float* __restrict__ b2,
             const __nv_bfloat16* __restrict__ W3, const float* __restrict__ b3,
             float* __restrict__ qenc)
{
    extern __shared__ char dsm[];
    __nv_bfloat16* A1  = reinterpret_cast<__nv_bfloat16*>(dsm);
    __nv_bfloat16* W1s = reinterpret_cast<__nv_bfloat16*>(dsm + 63488);
    __nv_bfloat16* H1  = reinterpret_cast<__nv_bfloat16*>(dsm + 142848);
    __nv_bfloat16* W2s = reinterpret_cast<__nv_bfloat16*>(dsm);
    __nv_bfloat16* H2  = reinterpret_cast<__nv_bfloat16*>(dsm + 26880);
    __nv_bfloat16* W3s = reinterpret_cast<__nv_bfloat16*>(dsm + 49408);

    const int tid  = threadIdx.x;
    const int wid  = tid >> 5;
    const int lane = tid & 31;
    const int n0   = blockIdx.x * 128;
    const int rowq = (lane & 15);
    const int kq8  = (lane >> 4) * 8;

    #pragma unroll
    for (int j = 0; j < 15; j++) {
        const int kl = (tid >> 5) + j * 16;
        const int ci = kl / 3;
        const int w  = kl - ci * 3;
        #pragma unroll
        for (int i = 0; i < 4; i++) {
            const int r  = ((tid & 31) << 2) + i;
            const int n  = n0 + r;
            const int bb = n / TQ;
            const int t  = n - bb * TQ;
            const int tg = t + w - 1;
            __nv_bfloat16 v = __float2bfloat16(0.f);
            if (tg >= 0 && tg < TQ) v = qbf[((size_t)bb * 80 + ci) * TQ + tg];
            A1[r * 248 + kl] = v;
        }
    }
    for (int e = tid; e < 160 * 60; e += 512) {
        const int r = e / 60;
        const int q = (e - r * 60) * 4;
        *reinterpret_cast<uint2*>(&W1s[r * 248 + q]) =
            *reinterpret_cast<const uint2*>(W1 + (size_t)r * 240 + q);
    }
    __syncthreads();

    {
        const int ng  = wid & 7;
        const int coh = (wid >> 3) * 80;
        const uint32_t a_addr = smem_to_u32(A1)  + ((ng * 16 + rowq) * 248 + kq8) * 2;
        const uint32_t b_addr = smem_to_u32(W1s) + ((coh + rowq) * 248 + kq8) * 2;
        float acc1[5][2][4];
        #pragma unroll
        for (int ct = 0; ct < 5; ct++)
            #pragma unroll
            for (int s = 0; s < 2; s++)
                #pragma unroll
                for (int i = 0; i < 4; i++) acc1[ct][s][i] = 0.f;
        #pragma unroll
        for (int ks = 0; ks < 15; ks++) {
            const uint32_t koff = ks * 32;
            uint32_t a0, a1, a2, a3;
            ldsm_x4(a0, a1, a2, a3, a_addr + koff);
            #pragma unroll
            for (int ct = 0; ct < 5; ct++) {
                uint32_t b0, b1, b2, b3;
                ldsm_x4(b0, b1, b2, b3, b_addr + ct * 16 * 248 * 2 + koff);
                mma_bf16(acc1[ct][0], a0, a1, a2, a3, b0, b2);
                mma_bf16(acc1[ct][1], a0, a1, a2, a3, b1, b3);
            }
        }
        __syncthreads();
        #pragma unroll
        for (int ct = 0; ct < 5; ct++)
            #pragma unroll
            for (int s = 0; s < 2; s++)
                #pragma unroll
                for (int i = 0; i < 4; i++) {
                    const int co = coh + ct * 16 + s * 8 + ((lane & 3) << 1) + (i & 1);
                    const int nl = ng * 16 + (lane >> 2) + ((i >> 1) << 3);
                    H1[nl * 168 + co] = __float2bfloat16(fmaxf(acc1[ct][s][i] + b1[co], 0.f));
                }
    }
    for (int e = tid; e < 80 * 40; e += 512) {
        const int r = e / 40;
        const int q = (e - r * 40) * 4;
        *reinterpret_cast<uint2*>(&W2s[r * 168 + q]) =
            *reinterpret_cast<const uint2*>(W2 + (size_t)r * 160 + q);
    }
    __syncthreads();

    if (wid >= 8) {
        for (int e = tid - 256; e < 80 * 20; e += 256) {
            const int r = e / 20;
            const int q = (e - r * 20) * 4;
            *reinterpret_cast<uint2*>(&W3s[r * 88 + q]) =
                *reinterpret_cast<const uint2*>(W3 + (size_t)r * 80 + q);
        }
    } else {
        const uint32_t a_addr = smem_to_u32(H1)  + ((wid * 16 + rowq) * 168 + kq8) * 2;
        const uint32_t b_addr = smem_to_u32(W2s) + (rowq * 168 + kq8) * 2;
        float acc2[5][2][4];
        #pragma unroll
        for (int ct = 0; ct < 5; ct++)
            #pragma unroll
            for (int s = 0; s < 2; s++)
                #pragma unroll
                for (int i = 0; i < 4; i++) acc2[ct][s][i] = 0.f;
        #pragma unroll
        for (int ks = 0; ks < 10; ks++) {
            const uint32_t koff = ks * 32;
            uint32_t a0, a1, a2, a3;
            ldsm_x4(a0, a1, a2, a3, a_addr + koff);
            #pragma unroll
            for (int ct = 0; ct < 5; ct++) {
                uint32_t b0, b1, b2, b3;
                ldsm_x4(b0, b1, b2, b3, b_addr + ct * 16 * 168 * 2 + koff);
                mma_bf16(acc2[ct][0], a0, a1, a2, a3, b0, b2);
                mma_bf16(acc2[ct][1], a0, a1, a2, a3, b1, b3);
            }
        }
        #pragma unroll
        for (int ct = 0; ct < 5; ct++)
            #pragma unroll
            for (int s = 0; s < 2; s++)
                #pragma unroll
                for (int i = 0; i < 4; i++) {
                    const int co = ct * 16 + s * 8 + ((lane & 3) << 1) + (i & 1);
                    const int nl = wid * 16 + (lane >> 2) + ((i >> 1) << 3);
                    H2[nl * 88 + co] = __float2bfloat16(fmaxf(acc2[ct][s][i] + b2[co], 0.f));
                }
    }
    __syncthreads();

    if (wid < 8) {
        const uint32_t a_addr = smem_to_u32(H2)  + ((wid * 16 + rowq) * 88 + kq8) * 2;
        const uint32_t b_addr = smem_to_u32(W3s) + (rowq * 88 + kq8) * 2;
        float acc3[5][2][4];
        #pragma unroll
        for (int ct = 0; ct < 5; ct++)
            #pragma unroll
            for (int s = 0; s < 2; s++)
                #pragma unroll
                for (int i = 0; i < 4; i++) acc3[ct][s][i] = 0.f;
        #pragma unroll
        for (int ks = 0; ks < 5; ks++) {
            const uint32_t koff = ks * 32;
            uint32_t a0, a1, a2, a3;
            ldsm_x4(a0, a1, a2, a3, a_addr + koff);
            #pragma unroll
            for (int ct = 0; ct < 5; ct++) {
                uint32_t b0, b1, b2, b3;
                ldsm_x4(b0, b1, b2, b3, b_addr + ct * 16 * 88 * 2 + koff);
                mma_bf16(acc3[ct][0], a0, a1, a2, a3, b0, b2);
                mma_bf16(acc3[ct][1], a0, a1, a2, a3, b1, b3);
            }
        }
        #pragma unroll
        for (int ct = 0; ct < 5; ct++)
            #pragma unroll
            for (int s = 0; s < 2; s++)
                #pragma unroll
                for (int i = 0; i < 4; i++) {
                    const int co = ct * 16 + s * 8 + ((lane & 3) << 1) + (i & 1);
                    const int n  = n0 + wid * 16 + (lane >> 2) + ((i >> 1) << 3);
                    const int bb = n / TQ;
                    const int t  = n - bb * TQ;
                    qenc[((size_t)bb * 80 + co) * TQ + t] = acc3[ct][s][i] + b3[co];
                }
    }
}

// ---------------------------------------------------------------------------
// Fused attention — Ks cached in bf16 smem (42 KB total -> 5 CTAs/SM).
// ---------------------------------------------------------------------------
static __device__ __forceinline__ float warp_max(float v) {
    #pragma unroll
    for (int o = 16; o > 0; o >>= 1) v = fmaxf(v, __shfl_xor_sync(0xffffffffu, v, o));
    return v;
}
static __device__ __forceinline__ float warp_sum(float v) {
    #pragma unroll
    for (int o = 16; o > 0; o >>= 1) v += __shfl_xor_sync(0xffffffffu, v, o);
    return v;
}

#define AT_SMEM (80 * TK * 2 + 32 * 81 * 4 + TK * 4)   // 43168

__global__ __launch_bounds__(256)
void attn_kernel(const float* __restrict__ qenc, const float* __restrict__ kenc,
                 const float* __restrict__ prior, const unsigned char* __restrict__ mask,
                 float* __restrict__ attn_out, float* __restrict__ logp_out)
{
    extern __shared__ char smc[];
    __nv_bfloat16* Ks = reinterpret_cast<__nv_bfloat16*>(smc);              // 80*200 bf16
    float* Qs  = reinterpret_cast<float*>(smc + 80 * TK * 2);               // 32*81 f32
    float* k2s = Qs + 32 * 81;                                              // 200 f32

    const int b   = blockIdx.y;
    const int q0  = blockIdx.x * 32;
    const int tid = threadIdx.x;

    // load keys_enc[b] -> bf16 smem (float4 loads, bf16x2 stores)
    const float* kb = kenc + (size_t)b * 80 * TK;
    for (int i = tid; i < 80 * TK / 4; i += 256) {
        const float4 v = reinterpret_cast<const float4*>(kb)[i];
        __nv_bfloat162* d = reinterpret_cast<__nv_bfloat162*>(Ks + i * 4);
        d[0] = __float22bfloat162_rn(make_float2(v.x, v.y));
        d[1] = __float22bfloat162_rn(make_float2(v.z, v.w));
    }

    const float* qb = qenc + (size_t)b * 80 * TQ;
    {
        const int ql = tid & 31;
        for (int c = tid >> 5; c < 80; c += 8)
            Qs[ql * 81 + c] = qb[c * TQ + q0 + ql];
    }
    __syncthreads();

    for (int k = tid; k < TK; k += 256) {
        float s = 0.f;
        #pragma unroll 8
        for (int c = 0; c < 80; c++) {
            const float v = __bfloat162float(Ks[c * TK + k]);
            s = fmaf(v, v, s);
        }
        k2s[k] = s;
    }
    __syncthreads();

    const int warp = tid >> 5, lane = tid & 31;
    constexpr int KI = 7;

    float s[4][KI];
    #pragma unroll
    for (int r = 0; r < 4; r++)
        #pragma unroll
        for (int i = 0; i < KI; i++) s[r][i] = 0.f;

    for (int c = 0; c < 80; c++) {
        float qv[4];
        #pragma unroll
        for (int r = 0; r < 4; r++) qv[r] = Qs[(warp * 4 + r) * 81 + c];
        float kv[KI];
        #pragma unroll
        for (int i = 0; i < 6; i++) kv[i] = __bfloat162float(Ks[c * TK + lane + 32 * i]);
        kv[6] = (lane < 8) ? __bfloat162float(Ks[c * TK + lane + 192]) : 0.f;
        #pragma unroll
        for (int r = 0; r < 4; r++)
            #pragma unroll
            for (int i = 0; i < KI; i++)
                s[r][i] = fmaf(qv[r], kv[i], s[r][i]);
    }

    const float NEG_INF = -CUDART_INF_F;
    #pragma unroll
    for (int r = 0; r < 4; r++) {
        const int q = q0 + warp * 4 + r;
        const size_t row = ((size_t)b * TQ + q) * TK;

        float m1 = NEG_INF;
        #pragma unroll
        for (int i = 0; i < KI; i++) {
            const int k = lane + 32 * i;
            const float sc = (k < TK) ? -5e-4f * (k2s[k] - 2.f * s[r][i]) : NEG_INF;
            s[r][i] = sc;
            m1 = fmaxf(m1, sc);
        }
        m1 = warp_max(m1);

        float e[KI];
        float se = 0.f;
        #pragma unroll
        for (int i = 0; i < KI; i++) {
            const int k = lane + 32 * i;
            if (k < TK) { e[i] = __expf(s[r][i] - m1); se += e[i]; }
        }
        se = warp_sum(se);
        const float lse = m1 + __logf(se);

        float se2 = 0.f;
        #pragma unroll
        for (int i = 0; i < KI; i++) {
            const int k = lane + 32 * i;
            if (k < TK) {
                const float pr = prior[row + k] + 1e-8f;
                logp_out[row + k] = s[r][i] - lse + __logf(pr);
                const float wv = mask[b * TK + k] ? 0.f : e[i] * pr;
                e[i] = wv;
                se2 += wv;
            }
        }
        se2 = warp_sum(se2);
        const float inv = 1.f / se2;
        #pragma unroll
        for (int i = 0; i < KI; i++) {
            const int k = lane + 32 * i;
            if (k < TK) attn_out[row + k] = e[i] * inv;
        }
    }
}

// ---------------------------------------------------------------------------
extern "C" void kernel_launch(void* const* d_in, const int* in_sizes, int n_in,
                              void* d_out, int out_size)
{
    const float* queries = (const float*)d_in[0];
    const float* keys    = (const float*)d_in[1];
    const unsigned char* mask = (const unsigned char*)d_in[3];
    const float* prior   = (const float*)d_in[4];
    const float* kW1 = (const float*)d_in[5];
    const float* kb1 = (const float*)d_in[6];
    const float* kW2 = (const float*)d_in[7];
    const float* kb2 = (const float*)d_in[8];
    const float* qW1 = (const float*)d_in[9];
    const float* qb1 = (const float*)d_in[10];
    const float* qW2 = (const float*)d_in[11];
    const float* qb2 = (const float*)d_in[12];
    const float* qW3 = (const float*)d_in[13];
    const float* qb3 = (const float*)d_in[14];

    float* out      = (float*)d_out;
    float* attn_out = out;
    float* logp_out = out + (size_t)BATCH * TQ * TK;

    __nv_bfloat16 *keysT, *qbf, *kW1bf, *kW2bf, *qW1bf, *qW2bf, *qW3bf;
    float *kenc, *qenc;
    cudaGetSymbolAddress((void**)&keysT, g_keysT);
    cudaGetSymbolAddress((void**)&qbf,   g_qbf);
    cudaGetSymbolAddress((void**)&kW1bf, g_kW1bf);
    cudaGetSymbolAddress((void**)&kW2bf, g_kW2bf);
    cudaGetSymbolAddress((void**)&qW1bf, g_qW1bf);
    cudaGetSymbolAddress((void**)&qW2bf, g_qW2bf);
    cudaGetSymbolAddress((void**)&qW3bf, g_qW3bf);
    cudaGetSymbolAddress((void**)&kenc,  g_kenc);
    cudaGetSymbolAddress((void**)&qenc,  g_qenc);

    static cudaStream_t sB = nullptr;
    static cudaEvent_t evFork = nullptr, evK = nullptr, evJoin = nullptr;
    if (sB == nullptr) {
        cudaStreamCreateWithFlags(&sB, cudaStreamNonBlocking);
        cudaEventCreateWithFlags(&evFork, cudaEventDisableTiming);
        cudaEventCreateWithFlags(&evK,    cudaEventDisableTiming);
        cudaEventCreateWithFlags(&evJoin, cudaEventDisableTiming);
        cudaFuncSetAttribute(conv1_fused, cudaFuncAttributeMaxDynamicSharedMemorySize, C1_SMEM);
        cudaFuncSetAttribute(fused_q,     cudaFuncAttributeMaxDynamicSharedMemorySize, QF_SMEM);
        cudaFuncSetAttribute(attn_kernel, cudaFuncAttributeMaxDynamicSharedMemorySize, AT_SMEM);
    }

    // ---- fork: stream B = init_kenc + convert_k (feed conv1), then query path ----
    cudaEventRecord(evFork, 0);
    cudaStreamWaitEvent(sB, evFork, 0);

    init_kenc<<<(BATCH * 80 * TK + 255) / 256, 256, 0, sB>>>(kb2);
    convert_k<<<(CK_TOT / 4 + 255) / 256, 256, 0, sB>>>(kW1, kW2);
    cudaEventRecord(evK, sB);
    convert_q<<<(CQ_TOT / 4 + 255) / 256, 256, 0, sB>>>(queries, qW1, qW2, qW3);
    fused_q<<<BATCH * TQ / 128, 512, QF_SMEM, sB>>>(qbf, qW1bf, qb1, qW2bf, qb2, qW3bf, qb3, qenc);
    cudaEventRecord(evJoin, sB);

    // ---- stream 0: keys path (transpose overlaps init/convert_k) ----
    transpose_keys<<<dim3(4, 4, BATCH), 256>>>(keys);
    cudaStreamWaitEvent(0, evK, 0);
    conv1_fused<<<dim3(BATCH * TK / 64, 1024 / 128), 256, C1_SMEM>>>(keysT, kW1bf, kb1, kW2bf, kenc);

    // ---- join, then attention ----
    cudaStreamWaitEvent(0, evJoin, 0);
    attn_kernel<<<dim3(TQ / 32, BATCH), 256, AT_SMEM>>>(qenc, kenc, prior, mask, attn_out, logp_out);
}